// round 2
// baseline (speedup 1.0000x reference)
#include <cuda_runtime.h>
#include <math.h>

#define B_ 64
#define D_ 512
#define N_ 1024
#define NH_ 8
#define DH_ 64

// Scratch (static device globals — no allocation allowed)
__device__ float g_qW[NH_][D_];        // 16 KB
__device__ float g_qb[NH_];
__device__ float g_qpe[NH_][N_];       // 32 KB
__device__ float g_dotsP[2][B_][NH_][N_];  // 4 MB (two c-half partials)
__device__ float g_attn[B_][NH_][N_];      // 2 MB
__device__ float g_w[B_][NH_][D_];         // 1 MB

// ---------------------------------------------------------------------------
// K0a: qW[h][c] = sum_d q[h,d] * Wkv[c, h*64+d]  (K half of Wkv: cols 0..511)
//      qb[h]    = sum_d q[h,d] * bkv[h*64+d]
// ---------------------------------------------------------------------------
__global__ void k_prep_qw(const float* __restrict__ q,
                          const float* __restrict__ Wkv,
                          const float* __restrict__ bkv) {
    int idx = blockIdx.x * 256 + threadIdx.x;   // 0..4095
    int h = idx >> 9;
    int c = idx & 511;
    float acc = 0.f;
#pragma unroll 8
    for (int d = 0; d < DH_; d++)
        acc = fmaf(q[h * DH_ + d], Wkv[(size_t)c * 1024 + h * DH_ + d], acc);
    g_qW[h][c] = acc;
    if (idx < NH_) {
        float s = 0.f;
        for (int d = 0; d < DH_; d++)
            s = fmaf(q[idx * DH_ + d], bkv[idx * DH_ + d], s);
        g_qb[idx] = s;
    }
}

// ---------------------------------------------------------------------------
// K0b: qpe[h][n] = sum_i q[h,2i]*sin(n*div_i) + q[h,2i+1]*cos(n*div_i)
// double precision so fast-math flags can't perturb the trig.
// ---------------------------------------------------------------------------
__global__ void k_prep_qpe(const float* __restrict__ q) {
    int idx = blockIdx.x * 256 + threadIdx.x;   // 0..8191
    int h = idx >> 10;
    int n = idx & 1023;
    double acc = 0.0;
#pragma unroll 8
    for (int i = 0; i < 32; i++) {
        double div = exp((double)(2 * i) * (-9.210340371976184 / 64.0));
        double a = (double)n * div;
        acc += (double)q[h * 64 + 2 * i] * sin(a)
             + (double)q[h * 64 + 2 * i + 1] * cos(a);
    }
    g_qpe[h][n] = (float)acc;
}

// ---------------------------------------------------------------------------
// K1: dots partials. grid = 128 (b=bid>>1, c-half=bid&1), 256 threads.
// Thread t owns n = 4t..4t+3 (float4). Loops over 256 c rows of this half.
// ---------------------------------------------------------------------------
__global__ void k_dots(const float* __restrict__ x) {
    int half = blockIdx.x & 1;
    int b = blockIdx.x >> 1;
    int t = threadIdx.x;
    __shared__ float sQW[256][8];
    int c0 = half * 256;
    for (int i = t; i < 256 * 8; i += 256) {
        int cl = i >> 3, h = i & 7;
        sQW[cl][h] = g_qW[h][c0 + cl];
    }
    __syncthreads();

    const float4* X = (const float4*)(x + (size_t)b * D_ * N_ + (size_t)c0 * N_);
    float ax[8], ay[8], az[8], aw[8];
#pragma unroll
    for (int h = 0; h < 8; h++) { ax[h] = ay[h] = az[h] = aw[h] = 0.f; }

#pragma unroll 4
    for (int c = 0; c < 256; c++) {
        float4 xv = X[c * 256 + t];
#pragma unroll
        for (int h = 0; h < 8; h++) {
            float w = sQW[c][h];
            ax[h] = fmaf(w, xv.x, ax[h]);
            ay[h] = fmaf(w, xv.y, ay[h]);
            az[h] = fmaf(w, xv.z, az[h]);
            aw[h] = fmaf(w, xv.w, aw[h]);
        }
    }
    float4* dst = (float4*)&g_dotsP[half][b][0][0];
#pragma unroll
    for (int h = 0; h < 8; h++)
        dst[h * 256 + t] = make_float4(ax[h], ay[h], az[h], aw[h]);
}

// ---------------------------------------------------------------------------
// K2: softmax over n=1024 per (b,h). grid = 512, 256 threads (4 n each).
// ---------------------------------------------------------------------------
__global__ void k_softmax() {
    int b = blockIdx.x >> 3;
    int h = blockIdx.x & 7;
    int t = threadIdx.x;
    int lane = t & 31, wid = t >> 5;
    __shared__ float red[8];
    __shared__ float bcast;

    float4 p0 = ((const float4*)&g_dotsP[0][b][h][0])[t];
    float4 p1 = ((const float4*)&g_dotsP[1][b][h][0])[t];
    float4 pe = ((const float4*)&g_qpe[h][0])[t];
    float qb = g_qb[h];
    const float scale = 0.125f;  // 64^-0.5

    float z0 = (p0.x + p1.x + pe.x + qb) * scale;
    float z1 = (p0.y + p1.y + pe.y + qb) * scale;
    float z2 = (p0.z + p1.z + pe.z + qb) * scale;
    float z3 = (p0.w + p1.w + pe.w + qb) * scale;

    float m = fmaxf(fmaxf(z0, z1), fmaxf(z2, z3));
#pragma unroll
    for (int off = 16; off; off >>= 1)
        m = fmaxf(m, __shfl_xor_sync(0xffffffffu, m, off));
    if (lane == 0) red[wid] = m;
    __syncthreads();
    if (t == 0) {
        float mm = red[0];
#pragma unroll
        for (int i = 1; i < 8; i++) mm = fmaxf(mm, red[i]);
        bcast = mm;
    }
    __syncthreads();
    float M = bcast;

    float e0 = __expf(z0 - M), e1 = __expf(z1 - M);
    float e2 = __expf(z2 - M), e3 = __expf(z3 - M);
    float s = e0 + e1 + e2 + e3;
#pragma unroll
    for (int off = 16; off; off >>= 1)
        s += __shfl_xor_sync(0xffffffffu, s, off);
    if (lane == 0) red[wid] = s;
    __syncthreads();
    if (t == 0) {
        float ss = 0.f;
#pragma unroll
        for (int i = 0; i < 8; i++) ss += red[i];
        bcast = ss;
    }
    __syncthreads();
    float inv = 1.0f / bcast;

    ((float4*)&g_attn[b][h][0])[t] =
        make_float4(e0 * inv, e1 * inv, e2 * inv, e3 * inv);
}

// ---------------------------------------------------------------------------
// K3: w[b,h,c] = sum_n attn[b,h,n] * x[b,c,n].
// grid = 1024 (b=bid>>4, chunk=bid&15 of 32 c-rows), 256 threads.
// Each warp owns 4 c-rows; attn tile reused across rows from smem (float4).
// ---------------------------------------------------------------------------
__global__ void k_wsum(const float* __restrict__ x) {
    int b = blockIdx.x >> 4;
    int chunk = blockIdx.x & 15;
    int t = threadIdx.x;
    int lane = t & 31, wid = t >> 5;
    __shared__ float sAttn[NH_ * N_];   // 32 KB

    const float4* A = (const float4*)&g_attn[b][0][0];
    float4* sA4 = (float4*)sAttn;
    for (int i = t; i < NH_ * N_ / 4; i += 256) sA4[i] = A[i];
    __syncthreads();

    int cbase = chunk * 32 + wid * 4;
    const float* xb = x + (size_t)b * D_ * N_;
    const float4* r0 = (const float4*)(xb + (size_t)(cbase + 0) * N_);
    const float4* r1 = (const float4*)(xb + (size_t)(cbase + 1) * N_);
    const float4* r2 = (const float4*)(xb + (size_t)(cbase + 2) * N_);
    const float4* r3 = (const float4*)(xb + (size_t)(cbase + 3) * N_);

    float acc[4][8];
#pragma unroll
    for (int r = 0; r < 4; r++)
#pragma unroll
        for (int h = 0; h < 8; h++) acc[r][h] = 0.f;

#pragma unroll
    for (int k = 0; k < 8; k++) {
        int idx = lane + 32 * k;
        float4 x0 = r0[idx], x1 = r1[idx], x2 = r2[idx], x3 = r3[idx];
#pragma unroll
        for (int h = 0; h < 8; h++) {
            float4 av = sA4[h * 256 + idx];
            acc[0][h] = fmaf(av.x, x0.x, acc[0][h]);
            acc[0][h] = fmaf(av.y, x0.y, acc[0][h]);
            acc[0][h] = fmaf(av.z, x0.z, acc[0][h]);
            acc[0][h] = fmaf(av.w, x0.w, acc[0][h]);
            acc[1][h] = fmaf(av.x, x1.x, acc[1][h]);
            acc[1][h] = fmaf(av.y, x1.y, acc[1][h]);
            acc[1][h] = fmaf(av.z, x1.z, acc[1][h]);
            acc[1][h] = fmaf(av.w, x1.w, acc[1][h]);
            acc[2][h] = fmaf(av.x, x2.x, acc[2][h]);
            acc[2][h] = fmaf(av.y, x2.y, acc[2][h]);
            acc[2][h] = fmaf(av.z, x2.z, acc[2][h]);
            acc[2][h] = fmaf(av.w, x2.w, acc[2][h]);
            acc[3][h] = fmaf(av.x, x3.x, acc[3][h]);
            acc[3][h] = fmaf(av.y, x3.y, acc[3][h]);
            acc[3][h] = fmaf(av.z, x3.z, acc[3][h]);
            acc[3][h] = fmaf(av.w, x3.w, acc[3][h]);
        }
    }

    // warp reduce each of the 32 partials; lane 0 stores
#pragma unroll
    for (int r = 0; r < 4; r++)
#pragma unroll
        for (int h = 0; h < 8; h++) {
#pragma unroll
            for (int off = 16; off; off >>= 1)
                acc[r][h] += __shfl_xor_sync(0xffffffffu, acc[r][h], off);
        }
    if (lane == 0) {
#pragma unroll
        for (int r = 0; r < 4; r++)
#pragma unroll
            for (int h = 0; h < 8; h++)
                g_w[b][h][cbase + r] = acc[r][h];
    }
}

// ---------------------------------------------------------------------------
// K4: out[b][h*64+d] = sum_c w[b,h,c] * Wkv[c, 512+h*64+d] + bkv[512+h*64+d]
// grid = 64, 512 threads (t = h*64+d).
// ---------------------------------------------------------------------------
__global__ void k_out(const float* __restrict__ Wkv,
                      const float* __restrict__ bkv,
                      float* __restrict__ out) {
    int b = blockIdx.x;
    int t = threadIdx.x;   // 0..511
    __shared__ float sw[NH_ * D_];  // 16 KB
    const float4* W4 = (const float4*)&g_w[b][0][0];
    float4* s4 = (float4*)sw;
    for (int i = t; i < NH_ * D_ / 4; i += 512) s4[i] = W4[i];
    __syncthreads();

    int h = t >> 6;
    float acc = bkv[512 + t];
    const float* Wv = Wkv + 512 + t;
    const float* swh = &sw[h * D_];
#pragma unroll 8
    for (int c = 0; c < 512; c++)
        acc = fmaf(swh[c], Wv[(size_t)c * 1024], acc);
    out[b * 512 + t] = acc;
}

// ---------------------------------------------------------------------------
extern "C" void kernel_launch(void* const* d_in, const int* in_sizes, int n_in,
                              void* d_out, int out_size) {
    const float* x   = (const float*)d_in[0];
    const float* q   = (const float*)d_in[1];
    const float* Wkv = (const float*)d_in[2];
    const float* bkv = (const float*)d_in[3];
    float* out = (float*)d_out;

    k_prep_qw<<<16, 256>>>(q, Wkv, bkv);
    k_prep_qpe<<<32, 256>>>(q);
    k_dots<<<128, 256>>>(x);
    k_softmax<<<512, 256>>>();
    k_wsum<<<1024, 256>>>(x);
    k_out<<<64, 512>>>(Wkv, bkv, out);
}

// round 3
// speedup vs baseline: 2.9294x; 2.9294x over previous
#include <cuda_runtime.h>
#include <math.h>

#define B_ 64
#define D_ 512
#define N_ 1024
#define NH_ 8
#define DH_ 64
#define CCHUNKS_ 8          // k_dots c-split
#define CROWS_ (D_ / CCHUNKS_)

// Scratch (static device globals — no allocation allowed)
__device__ float g_qW[NH_][D_];                    // 16 KB
__device__ float g_qb[NH_];
__device__ float g_qpe[NH_][N_];                   // 32 KB
__device__ float g_dotsP[CCHUNKS_][B_][NH_][N_];   // 16 MB
__device__ float g_attn[B_][NH_][N_];              // 2 MB
__device__ float g_w[B_][NH_][D_];                 // 1 MB

// ---------------------------------------------------------------------------
// K0 (fused prep): blocks 0..15 -> qW/qb, blocks 16..47 -> qpe (fp32, matching
// the reference's float32 arithmetic; doubles were pure FP64-pipe poison).
// ---------------------------------------------------------------------------
__global__ void k_prep(const float* __restrict__ q,
                       const float* __restrict__ Wkv,
                       const float* __restrict__ bkv) {
    if (blockIdx.x < 16) {
        int idx = blockIdx.x * 256 + threadIdx.x;   // 0..4095
        int h = idx >> 9;
        int c = idx & 511;
        const float4* qr = (const float4*)(q + h * DH_);
        const float4* wr = (const float4*)(Wkv + (size_t)c * 1024 + h * DH_);
        float acc = 0.f;
#pragma unroll
        for (int d4 = 0; d4 < DH_ / 4; d4++) {
            float4 qa = qr[d4], wa = wr[d4];
            acc = fmaf(qa.x, wa.x, acc);
            acc = fmaf(qa.y, wa.y, acc);
            acc = fmaf(qa.z, wa.z, acc);
            acc = fmaf(qa.w, wa.w, acc);
        }
        g_qW[h][c] = acc;
        if (idx < NH_) {
            float s = 0.f;
            for (int d = 0; d < DH_; d++)
                s = fmaf(q[idx * DH_ + d], bkv[idx * DH_ + d], s);
            g_qb[idx] = s;
        }
    } else {
        int idx = (blockIdx.x - 16) * 256 + threadIdx.x;  // 0..8191
        int h = idx >> 10;
        int n = idx & 1023;
        float acc = 0.f;
        float fn = (float)n;
#pragma unroll 8
        for (int i = 0; i < 32; i++) {
            float div = expf((float)(2 * i) * (-9.210340371976184f / 64.0f));
            float s, c;
            sincosf(fn * div, &s, &c);
            acc = fmaf(q[h * 64 + 2 * i], s, acc);
            acc = fmaf(q[h * 64 + 2 * i + 1], c, acc);
        }
        g_qpe[h][n] = acc;
    }
}

// ---------------------------------------------------------------------------
// K1: dots partials. grid = B*8 = 512 (b=bid>>3, chunk=bid&7), 256 threads.
// Thread t owns n = 4t..4t+3 (float4); 64 c-rows per chunk, unroll 8 for MLP.
// ---------------------------------------------------------------------------
__global__ void k_dots(const float* __restrict__ x) {
    int chunk = blockIdx.x & 7;
    int b = blockIdx.x >> 3;
    int t = threadIdx.x;
    __shared__ float sQW[CROWS_][8];
    int c0 = chunk * CROWS_;
    for (int i = t; i < CROWS_ * 8; i += 256) {
        int cl = i >> 3, h = i & 7;
        sQW[cl][h] = g_qW[h][c0 + cl];
    }
    __syncthreads();

    const float4* X = (const float4*)(x + (size_t)b * D_ * N_ + (size_t)c0 * N_);
    float ax[8], ay[8], az[8], aw[8];
#pragma unroll
    for (int h = 0; h < 8; h++) { ax[h] = ay[h] = az[h] = aw[h] = 0.f; }

#pragma unroll 8
    for (int c = 0; c < CROWS_; c++) {
        float4 xv = X[c * 256 + t];
#pragma unroll
        for (int h = 0; h < 8; h++) {
            float w = sQW[c][h];
            ax[h] = fmaf(w, xv.x, ax[h]);
            ay[h] = fmaf(w, xv.y, ay[h]);
            az[h] = fmaf(w, xv.z, az[h]);
            aw[h] = fmaf(w, xv.w, aw[h]);
        }
    }
    float4* dst = (float4*)&g_dotsP[chunk][b][0][0];
#pragma unroll
    for (int h = 0; h < 8; h++)
        dst[h * 256 + t] = make_float4(ax[h], ay[h], az[h], aw[h]);
}

// ---------------------------------------------------------------------------
// K2: softmax over n=1024 per (b,h). grid = 512, 256 threads (4 n each).
// ---------------------------------------------------------------------------
__global__ void k_softmax() {
    int b = blockIdx.x >> 3;
    int h = blockIdx.x & 7;
    int t = threadIdx.x;
    int lane = t & 31, wid = t >> 5;
    __shared__ float red[8];
    __shared__ float bcast;

    float4 pe = ((const float4*)&g_qpe[h][0])[t];
    float qb = g_qb[h];
    float z0 = pe.x + qb, z1 = pe.y + qb, z2 = pe.z + qb, z3 = pe.w + qb;
#pragma unroll
    for (int j = 0; j < CCHUNKS_; j++) {
        float4 p = ((const float4*)&g_dotsP[j][b][h][0])[t];
        z0 += p.x; z1 += p.y; z2 += p.z; z3 += p.w;
    }
    const float scale = 0.125f;  // 64^-0.5
    z0 *= scale; z1 *= scale; z2 *= scale; z3 *= scale;

    float m = fmaxf(fmaxf(z0, z1), fmaxf(z2, z3));
#pragma unroll
    for (int off = 16; off; off >>= 1)
        m = fmaxf(m, __shfl_xor_sync(0xffffffffu, m, off));
    if (lane == 0) red[wid] = m;
    __syncthreads();
    if (t == 0) {
        float mm = red[0];
#pragma unroll
        for (int i = 1; i < 8; i++) mm = fmaxf(mm, red[i]);
        bcast = mm;
    }
    __syncthreads();
    float M = bcast;

    float e0 = __expf(z0 - M), e1 = __expf(z1 - M);
    float e2 = __expf(z2 - M), e3 = __expf(z3 - M);
    float s = e0 + e1 + e2 + e3;
#pragma unroll
    for (int off = 16; off; off >>= 1)
        s += __shfl_xor_sync(0xffffffffu, s, off);
    if (lane == 0) red[wid] = s;
    __syncthreads();
    if (t == 0) {
        float ss = 0.f;
#pragma unroll
        for (int i = 0; i < 8; i++) ss += red[i];
        bcast = ss;
    }
    __syncthreads();
    float inv = 1.0f / bcast;

    ((float4*)&g_attn[b][h][0])[t] =
        make_float4(e0 * inv, e1 * inv, e2 * inv, e3 * inv);
}

// ---------------------------------------------------------------------------
// K3: w[b,h,c] = sum_n attn[b,h,n] * x[b,c,n].
// grid = 1024 (b=bid>>4, chunk=bid&15 of 32 c-rows), 256 threads.
// Each warp owns 4 c-rows x 8 heads = 32 partials; butterfly multi-value
// reduce (31 SHFLs) leaves lane l holding result l; per-lane store.
// ---------------------------------------------------------------------------
__global__ void k_wsum(const float* __restrict__ x) {
    int b = blockIdx.x >> 4;
    int chunk = blockIdx.x & 15;
    int t = threadIdx.x;
    int lane = t & 31, wid = t >> 5;
    __shared__ float sAttn[NH_ * N_];   // 32 KB

    const float4* A = (const float4*)&g_attn[b][0][0];
    float4* sA4 = (float4*)sAttn;
    for (int i = t; i < NH_ * N_ / 4; i += 256) sA4[i] = A[i];
    __syncthreads();

    int cbase = chunk * 32 + wid * 4;
    const float* xb = x + (size_t)b * D_ * N_;
    const float4* r0 = (const float4*)(xb + (size_t)(cbase + 0) * N_);
    const float4* r1 = (const float4*)(xb + (size_t)(cbase + 1) * N_);
    const float4* r2 = (const float4*)(xb + (size_t)(cbase + 2) * N_);
    const float4* r3 = (const float4*)(xb + (size_t)(cbase + 3) * N_);

    float v[32];   // v[r*8+h]
#pragma unroll
    for (int i = 0; i < 32; i++) v[i] = 0.f;

#pragma unroll
    for (int k = 0; k < 8; k++) {
        int idx = lane + 32 * k;
        float4 x0 = r0[idx], x1 = r1[idx], x2 = r2[idx], x3 = r3[idx];
#pragma unroll
        for (int h = 0; h < 8; h++) {
            float4 av = sA4[h * 256 + idx];
            v[0 * 8 + h] = fmaf(av.x, x0.x, v[0 * 8 + h]);
            v[0 * 8 + h] = fmaf(av.y, x0.y, v[0 * 8 + h]);
            v[0 * 8 + h] = fmaf(av.z, x0.z, v[0 * 8 + h]);
            v[0 * 8 + h] = fmaf(av.w, x0.w, v[0 * 8 + h]);
            v[1 * 8 + h] = fmaf(av.x, x1.x, v[1 * 8 + h]);
            v[1 * 8 + h] = fmaf(av.y, x1.y, v[1 * 8 + h]);
            v[1 * 8 + h] = fmaf(av.z, x1.z, v[1 * 8 + h]);
            v[1 * 8 + h] = fmaf(av.w, x1.w, v[1 * 8 + h]);
            v[2 * 8 + h] = fmaf(av.x, x2.x, v[2 * 8 + h]);
            v[2 * 8 + h] = fmaf(av.y, x2.y, v[2 * 8 + h]);
            v[2 * 8 + h] = fmaf(av.z, x2.z, v[2 * 8 + h]);
            v[2 * 8 + h] = fmaf(av.w, x2.w, v[2 * 8 + h]);
            v[3 * 8 + h] = fmaf(av.x, x3.x, v[3 * 8 + h]);
            v[3 * 8 + h] = fmaf(av.y, x3.y, v[3 * 8 + h]);
            v[3 * 8 + h] = fmaf(av.z, x3.z, v[3 * 8 + h]);
            v[3 * 8 + h] = fmaf(av.w, x3.w, v[3 * 8 + h]);
        }
    }

    // Butterfly multi-value allreduce: lane l ends with total for index l.
#pragma unroll
    for (int off = 16; off > 0; off >>= 1) {
#pragma unroll
        for (int i = 0; i < off; i++) {
            float a = v[i];
            float bb = v[i + off];
            float mine  = (lane & off) ? bb : a;
            float send  = (lane & off) ? a : bb;
            float recv = __shfl_xor_sync(0xffffffffu, send, off);
            v[i] = mine + recv;
        }
    }
    // lane l holds result for r = l>>3, h = l&7
    g_w[b][lane & 7][cbase + (lane >> 3)] = v[0];
}

// ---------------------------------------------------------------------------
// K4: out[b][t] = sum_c w[b,h(t),c] * Wkv[c, 512+t] + bkv[512+t]
// grid = 64, 1024 threads: tid = half*512 + t; each half sums 256 c; smem add.
// ---------------------------------------------------------------------------
__global__ void k_out(const float* __restrict__ Wkv,
                      const float* __restrict__ bkv,
                      float* __restrict__ out) {
    int b = blockIdx.x;
    int tid = threadIdx.x;          // 0..1023
    int t = tid & 511;
    int half = tid >> 9;
    __shared__ float sw[NH_ * D_];   // 16 KB
    __shared__ float spart[512];
    const float4* W4 = (const float4*)&g_w[b][0][0];
    float4* s4 = (float4*)sw;
    for (int i = tid; i < NH_ * D_ / 4; i += 1024) s4[i] = W4[i];
    __syncthreads();

    int h = t >> 6;
    int c0 = half * 256;
    float acc = 0.f;
    const float* Wv = Wkv + 512 + t + (size_t)c0 * 1024;
    const float* swh = &sw[h * D_ + c0];
#pragma unroll 8
    for (int c = 0; c < 256; c++)
        acc = fmaf(swh[c], Wv[(size_t)c * 1024], acc);

    if (half) spart[t] = acc;
    __syncthreads();
    if (!half)
        out[b * 512 + t] = acc + spart[t] + bkv[512 + t];
}

// ---------------------------------------------------------------------------
extern "C" void kernel_launch(void* const* d_in, const int* in_sizes, int n_in,
                              void* d_out, int out_size) {
    const float* x   = (const float*)d_in[0];
    const float* q   = (const float*)d_in[1];
    const float* Wkv = (const float*)d_in[2];
    const float* bkv = (const float*)d_in[3];
    float* out = (float*)d_out;

    k_prep<<<48, 256>>>(q, Wkv, bkv);
    k_dots<<<B_ * CCHUNKS_, 256>>>(x);
    k_softmax<<<512, 256>>>();
    k_wsum<<<1024, 256>>>(x);
    k_out<<<64, 1024>>>(Wkv, bkv, out);
}

// round 4
// speedup vs baseline: 3.4600x; 1.1811x over previous
#include <cuda_runtime.h>
#include <math.h>

#define B_ 64
#define D_ 512
#define N_ 1024
#define NH_ 8
#define DH_ 64
#define CCHUNKS_ 8          // k_dots c-split
#define CROWS_ (D_ / CCHUNKS_)

// Scratch (static device globals — no allocation allowed)
__device__ float g_qW[NH_][D_];                    // 16 KB
__device__ float g_qb[NH_];
__device__ float g_qpe[NH_][N_];                   // 32 KB
__device__ float g_dotsP[CCHUNKS_][B_][NH_][N_];   // 16 MB
__device__ float g_attn[B_][NH_][N_];              // 2 MB
__device__ float g_w[B_][NH_][D_];                 // 1 MB

// ---------------------------------------------------------------------------
// K0 (fused prep): blocks 0..15 -> qW/qb, blocks 16..47 -> qpe (fp32).
// ---------------------------------------------------------------------------
__global__ void k_prep(const float* __restrict__ q,
                       const float* __restrict__ Wkv,
                       const float* __restrict__ bkv) {
    if (blockIdx.x < 16) {
        int idx = blockIdx.x * 256 + threadIdx.x;   // 0..4095
        int h = idx >> 9;
        int c = idx & 511;
        const float4* qr = (const float4*)(q + h * DH_);
        const float4* wr = (const float4*)(Wkv + (size_t)c * 1024 + h * DH_);
        float acc = 0.f;
#pragma unroll
        for (int d4 = 0; d4 < DH_ / 4; d4++) {
            float4 qa = qr[d4], wa = wr[d4];
            acc = fmaf(qa.x, wa.x, acc);
            acc = fmaf(qa.y, wa.y, acc);
            acc = fmaf(qa.z, wa.z, acc);
            acc = fmaf(qa.w, wa.w, acc);
        }
        g_qW[h][c] = acc;
        if (idx < NH_) {
            float s = 0.f;
            for (int d = 0; d < DH_; d++)
                s = fmaf(q[idx * DH_ + d], bkv[idx * DH_ + d], s);
            g_qb[idx] = s;
        }
    } else {
        int idx = (blockIdx.x - 16) * 256 + threadIdx.x;  // 0..8191
        int h = idx >> 10;
        int n = idx & 1023;
        float acc = 0.f;
        float fn = (float)n;
#pragma unroll 8
        for (int i = 0; i < 32; i++) {
            float div = expf((float)(2 * i) * (-9.210340371976184f / 64.0f));
            float s, c;
            sincosf(fn * div, &s, &c);
            acc = fmaf(q[h * 64 + 2 * i], s, acc);
            acc = fmaf(q[h * 64 + 2 * i + 1], c, acc);
        }
        g_qpe[h][n] = acc;
    }
}

// ---------------------------------------------------------------------------
// K1: dots partials. grid = B*8 = 512 (b=bid>>3, chunk=bid&7), 256 threads.
// Thread t owns n = 4t..4t+3 (float4); 64 c-rows per chunk, unroll 8 for MLP.
// ---------------------------------------------------------------------------
__global__ void __launch_bounds__(256, 4) k_dots(const float* __restrict__ x) {
    int chunk = blockIdx.x & 7;
    int b = blockIdx.x >> 3;
    int t = threadIdx.x;
    __shared__ float sQW[CROWS_][8];
    int c0 = chunk * CROWS_;
    for (int i = t; i < CROWS_ * 8; i += 256) {
        int cl = i >> 3, h = i & 7;
        sQW[cl][h] = g_qW[h][c0 + cl];
    }
    __syncthreads();

    const float4* X = (const float4*)(x + (size_t)b * D_ * N_ + (size_t)c0 * N_);
    float ax[8], ay[8], az[8], aw[8];
#pragma unroll
    for (int h = 0; h < 8; h++) { ax[h] = ay[h] = az[h] = aw[h] = 0.f; }

#pragma unroll 8
    for (int c = 0; c < CROWS_; c++) {
        float4 xv = X[c * 256 + t];
#pragma unroll
        for (int h = 0; h < 8; h++) {
            float w = sQW[c][h];
            ax[h] = fmaf(w, xv.x, ax[h]);
            ay[h] = fmaf(w, xv.y, ay[h]);
            az[h] = fmaf(w, xv.z, az[h]);
            aw[h] = fmaf(w, xv.w, aw[h]);
        }
    }
    float4* dst = (float4*)&g_dotsP[chunk][b][0][0];
#pragma unroll
    for (int h = 0; h < 8; h++)
        dst[h * 256 + t] = make_float4(ax[h], ay[h], az[h], aw[h]);
}

// ---------------------------------------------------------------------------
// K2: softmax over n=1024 per (b,h). grid = 512, 256 threads (4 n each).
// ---------------------------------------------------------------------------
__global__ void k_softmax() {
    int b = blockIdx.x >> 3;
    int h = blockIdx.x & 7;
    int t = threadIdx.x;
    int lane = t & 31, wid = t >> 5;
    __shared__ float red[8];
    __shared__ float bcast;

    float4 pe = ((const float4*)&g_qpe[h][0])[t];
    float qb = g_qb[h];
    float z0 = pe.x + qb, z1 = pe.y + qb, z2 = pe.z + qb, z3 = pe.w + qb;
#pragma unroll
    for (int j = 0; j < CCHUNKS_; j++) {
        float4 p = ((const float4*)&g_dotsP[j][b][h][0])[t];
        z0 += p.x; z1 += p.y; z2 += p.z; z3 += p.w;
    }
    const float scale = 0.125f;  // 64^-0.5
    z0 *= scale; z1 *= scale; z2 *= scale; z3 *= scale;

    float m = fmaxf(fmaxf(z0, z1), fmaxf(z2, z3));
#pragma unroll
    for (int off = 16; off; off >>= 1)
        m = fmaxf(m, __shfl_xor_sync(0xffffffffu, m, off));
    if (lane == 0) red[wid] = m;
    __syncthreads();
    if (t == 0) {
        float mm = red[0];
#pragma unroll
        for (int i = 1; i < 8; i++) mm = fmaxf(mm, red[i]);
        bcast = mm;
    }
    __syncthreads();
    float M = bcast;

    float e0 = __expf(z0 - M), e1 = __expf(z1 - M);
    float e2 = __expf(z2 - M), e3 = __expf(z3 - M);
    float s = e0 + e1 + e2 + e3;
#pragma unroll
    for (int off = 16; off; off >>= 1)
        s += __shfl_xor_sync(0xffffffffu, s, off);
    if (lane == 0) red[wid] = s;
    __syncthreads();
    if (t == 0) {
        float ss = 0.f;
#pragma unroll
        for (int i = 0; i < 8; i++) ss += red[i];
        bcast = ss;
    }
    __syncthreads();
    float inv = 1.0f / bcast;

    ((float4*)&g_attn[b][h][0])[t] =
        make_float4(e0 * inv, e1 * inv, e2 * inv, e3 * inv);
}

// ---------------------------------------------------------------------------
// K3: w[b,h,c] = sum_n attn[b,h,n] * x[b,c,n].
// grid = 2048 (b=bid>>5, chunk=bid&31 of 16 c-rows), 256 threads.
// Each warp owns 2 c-rows x 8 heads = 16 partials -> fewer regs, 4 CTAs/SM.
// Butterfly multi-value reduce: lane pair (2l,2l+1) ends holding result l.
// ---------------------------------------------------------------------------
__global__ void __launch_bounds__(256, 4) k_wsum(const float* __restrict__ x) {
    int b = blockIdx.x >> 5;
    int chunk = blockIdx.x & 31;
    int t = threadIdx.x;
    int lane = t & 31, wid = t >> 5;
    __shared__ float sAttn[NH_ * N_];   // 32 KB

    const float4* A = (const float4*)&g_attn[b][0][0];
    float4* sA4 = (float4*)sAttn;
    for (int i = t; i < NH_ * N_ / 4; i += 256) sA4[i] = A[i];
    __syncthreads();

    int cbase = chunk * 16 + wid * 2;
    const float* xb = x + (size_t)b * D_ * N_;
    const float4* r0 = (const float4*)(xb + (size_t)(cbase + 0) * N_);
    const float4* r1 = (const float4*)(xb + (size_t)(cbase + 1) * N_);

    float v[16];   // v[h] for row0, v[8+h] for row1
#pragma unroll
    for (int i = 0; i < 16; i++) v[i] = 0.f;

#pragma unroll 4
    for (int k = 0; k < 8; k++) {
        int idx = lane + 32 * k;
        float4 x0 = r0[idx], x1 = r1[idx];
#pragma unroll
        for (int h = 0; h < 8; h++) {
            float4 av = sA4[h * 256 + idx];
            v[h]     = fmaf(av.x, x0.x, v[h]);
            v[h]     = fmaf(av.y, x0.y, v[h]);
            v[h]     = fmaf(av.z, x0.z, v[h]);
            v[h]     = fmaf(av.w, x0.w, v[h]);
            v[8 + h] = fmaf(av.x, x1.x, v[8 + h]);
            v[8 + h] = fmaf(av.y, x1.y, v[8 + h]);
            v[8 + h] = fmaf(av.z, x1.z, v[8 + h]);
            v[8 + h] = fmaf(av.w, x1.w, v[8 + h]);
        }
    }

    // Butterfly multi-value reduce: 16 values -> 1 per lane-pair.
    // Stage off=16: 16 -> 8
#pragma unroll
    for (int i = 0; i < 8; i++) {
        float a = v[i], bb = v[i + 8];
        float mine = (lane & 16) ? bb : a;
        float send = (lane & 16) ? a : bb;
        v[i] = mine + __shfl_xor_sync(0xffffffffu, send, 16);
    }
    // Stage off=8: 8 -> 4
#pragma unroll
    for (int i = 0; i < 4; i++) {
        float a = v[i], bb = v[i + 4];
        float mine = (lane & 8) ? bb : a;
        float send = (lane & 8) ? a : bb;
        v[i] = mine + __shfl_xor_sync(0xffffffffu, send, 8);
    }
    // Stage off=4: 4 -> 2
#pragma unroll
    for (int i = 0; i < 2; i++) {
        float a = v[i], bb = v[i + 2];
        float mine = (lane & 4) ? bb : a;
        float send = (lane & 4) ? a : bb;
        v[i] = mine + __shfl_xor_sync(0xffffffffu, send, 4);
    }
    // Stage off=2: 2 -> 1
    {
        float a = v[0], bb = v[1];
        float mine = (lane & 2) ? bb : a;
        float send = (lane & 2) ? a : bb;
        v[0] = mine + __shfl_xor_sync(0xffffffffu, send, 2);
    }
    // Stage off=1: lane pair holds same index -> plain add
    v[0] += __shfl_xor_sync(0xffffffffu, v[0], 1);

    // index i = lane>>1 (0..15): h = i&7, row = i>>3
    if (!(lane & 1)) {
        int i = lane >> 1;
        g_w[b][i & 7][cbase + (i >> 3)] = v[0];
    }
}

// ---------------------------------------------------------------------------
// K4: out[b][t] = sum_c w[b,h(t),c] * Wkv[c, 512+t] + bkv[512+t]
// grid = 64, 1024 threads: tid = half*512 + t; each half sums 256 c; smem add.
// ---------------------------------------------------------------------------
__global__ void k_out(const float* __restrict__ Wkv,
                      const float* __restrict__ bkv,
                      float* __restrict__ out) {
    int b = blockIdx.x;
    int tid = threadIdx.x;          // 0..1023
    int t = tid & 511;
    int half = tid >> 9;
    __shared__ float sw[NH_ * D_];   // 16 KB
    __shared__ float spart[512];
    const float4* W4 = (const float4*)&g_w[b][0][0];
    float4* s4 = (float4*)sw;
    for (int i = tid; i < NH_ * D_ / 4; i += 1024) s4[i] = W4[i];
    __syncthreads();

    int h = t >> 6;
    int c0 = half * 256;
    float acc = 0.f;
    const float* Wv = Wkv + 512 + t + (size_t)c0 * 1024;
    const float* swh = &sw[h * D_ + c0];
#pragma unroll 8
    for (int c = 0; c < 256; c++)
        acc = fmaf(swh[c], Wv[(size_t)c * 1024], acc);

    if (half) spart[t] = acc;
    __syncthreads();
    if (!half)
        out[b * 512 + t] = acc + spart[t] + bkv[512 + t];
}

// ---------------------------------------------------------------------------
extern "C" void kernel_launch(void* const* d_in, const int* in_sizes, int n_in,
                              void* d_out, int out_size) {
    const float* x   = (const float*)d_in[0];
    const float* q   = (const float*)d_in[1];
    const float* Wkv = (const float*)d_in[2];
    const float* bkv = (const float*)d_in[3];
    float* out = (float*)d_out;

    k_prep<<<48, 256>>>(q, Wkv, bkv);
    k_dots<<<B_ * CCHUNKS_, 256>>>(x);
    k_softmax<<<512, 256>>>();
    k_wsum<<<B_ * 32, 256>>>(x);
    k_out<<<64, 1024>>>(Wkv, bkv, out);
}